// round 10
// baseline (speedup 1.0000x reference)
#include <cuda_runtime.h>
#include <math.h>

#define BB 256   // batch
#define NS 32    // spans
#define DD 512   // feature dim

#define KT 32    // k-chunk per gemm block (16 k-splits)

// Scratch (allocation-free rule: __device__ globals)
__device__ float g_A[BB * DD];        // ner span-sums [b][d] row-major, pre-scaled 1/1024
__device__ float g_F[BB * DD];        // face span-sums [c][d] row-major
__device__ float g_logits[BB * BB];   // materialized logits (atomic k-split combine)
__device__ float g_diag[BB];          // logp[b][b]
__device__ unsigned int g_cnt;        // gemm-block arrival counter
__device__ unsigned int g_cnt2;       // lse-slice arrival counter

// ---------------------------------------------------------------------------
// Kernel 1: span reductions. 512 blocks x 512 threads.
// Thread = (d4, span-group). 4 partial sums combined in shared memory.
// BOTH outputs stored row-major with coalesced float4 stores (scattered
// 4B transposed stores in R8 poisoned DRAM with write sectors).
// Also zeroes g_logits / counters (runs strictly before kernel 2).
// ---------------------------------------------------------------------------
__global__ void reduce_spans(const float* __restrict__ face,
                             const float* __restrict__ ner) {
    const int blk = blockIdx.x;
    const int tid = threadIdx.x;
    const int t4  = tid & 127;     // float4 index within row (128 * 4 = 512 d)
    const int grp = tid >> 7;      // span group 0..3 (8 spans each)

    // zero logits: 128 blocks x 512 threads = 65536 floats
    if (blk < 128) g_logits[blk * 512 + tid] = 0.f;
    if (blk == 128 && tid == 0) { g_cnt = 0u; g_cnt2 = 0u; }

    const bool is_ner = (blk < BB);
    const int row = is_ner ? blk : blk - BB;
    const float4* src = reinterpret_cast<const float4*>(
        (is_ner ? ner : face) + (size_t)row * NS * DD);

    float4 s = make_float4(0.f, 0.f, 0.f, 0.f);
#pragma unroll
    for (int n = 0; n < 8; n++) {
        float4 v = src[(grp * 8 + n) * (DD / 4) + t4];
        s.x += v.x; s.y += v.y; s.z += v.z; s.w += v.w;
    }

    __shared__ float4 sp[3][128];
    if (grp > 0) sp[grp - 1][t4] = s;
    __syncthreads();

    if (grp == 0) {
#pragma unroll
        for (int i = 0; i < 3; i++) {
            float4 v = sp[i][t4];
            s.x += v.x; s.y += v.y; s.z += v.z; s.w += v.w;
        }
        if (is_ner) {
            const float inv = 1.0f / 1024.0f;   // fold the 1/(N1*N2) mean
            s.x *= inv; s.y *= inv; s.z *= inv; s.w *= inv;
            reinterpret_cast<float4*>(g_A + row * DD)[t4] = s;
        } else {
            reinterpret_cast<float4*>(g_F + row * DD)[t4] = s;
        }
    }
}

// ---------------------------------------------------------------------------
// Kernel 2: smem-staged register-blocked SGEMM partial + fused LSE.
// Block = 64x64 C-tile, k-chunk of 32. Grid = 16 tiles x 16 k-splits = 256
// blocks x 256 threads (single co-resident wave -> safe device-side spin).
// Staging: coalesced float4 L2 reads of row-major tiles, transposed STS.
// Mainloop per k: 2 x LDS.128 + 16 FMA. Combine via atomicAdd (REDG).
// Last 32 arriving blocks spin for full combine, then do per-row LSE
// (8 rows each); last LSE slice computes the final mean.
// ---------------------------------------------------------------------------
__global__ void gemm_lse(float* __restrict__ out) {
    const int bx = blockIdx.x;
    const int kq = bx >> 4;              // k-split 0..15
    const int rt = (bx >> 2) & 3;        // row tile 0..3
    const int ct = bx & 3;               // col tile 0..3
    const int kb = kq * KT;
    const int r0 = rt * 64;
    const int c0 = ct * 64;
    const int tid = threadIdx.x;

    __shared__ float sA[KT][64];         // sA[k][row]  8 KB
    __shared__ float sB[KT][64];         // sB[k][col]  8 KB

    // Staging with in-smem transpose. Reads coalesced: warp covers 4
    // consecutive rows x 8 float4 (row segment kb..kb+31 = 128B contiguous).
#pragma unroll
    for (int j = 0; j < 2; j++) {
        const int idx = j * 256 + tid;   // 0..511
        const int row = idx >> 3;        // 0..63
        const int k4  = idx & 7;         // float4 along k-chunk
        const float4 va = *reinterpret_cast<const float4*>(
            g_A + (r0 + row) * DD + kb + k4 * 4);
        sA[k4 * 4 + 0][row] = va.x;
        sA[k4 * 4 + 1][row] = va.y;
        sA[k4 * 4 + 2][row] = va.z;
        sA[k4 * 4 + 3][row] = va.w;
        const float4 vb = *reinterpret_cast<const float4*>(
            g_F + (c0 + row) * DD + kb + k4 * 4);
        sB[k4 * 4 + 0][row] = vb.x;
        sB[k4 * 4 + 1][row] = vb.y;
        sB[k4 * 4 + 2][row] = vb.z;
        sB[k4 * 4 + 3][row] = vb.w;
    }
    __syncthreads();

    const int ty = tid >> 4;             // 0..15 -> rows r0 + ty*4 ..
    const int tx = tid & 15;             // 0..15 -> cols c0 + tx*4 ..

    float acc[4][4];
#pragma unroll
    for (int i = 0; i < 4; i++)
#pragma unroll
        for (int j = 0; j < 4; j++) acc[i][j] = 0.f;

#pragma unroll
    for (int k = 0; k < KT; k++) {
        const float4 a = *reinterpret_cast<const float4*>(&sA[k][ty * 4]);
        const float4 b = *reinterpret_cast<const float4*>(&sB[k][tx * 4]);
        acc[0][0] = fmaf(a.x, b.x, acc[0][0]);
        acc[0][1] = fmaf(a.x, b.y, acc[0][1]);
        acc[0][2] = fmaf(a.x, b.z, acc[0][2]);
        acc[0][3] = fmaf(a.x, b.w, acc[0][3]);
        acc[1][0] = fmaf(a.y, b.x, acc[1][0]);
        acc[1][1] = fmaf(a.y, b.y, acc[1][1]);
        acc[1][2] = fmaf(a.y, b.z, acc[1][2]);
        acc[1][3] = fmaf(a.y, b.w, acc[1][3]);
        acc[2][0] = fmaf(a.z, b.x, acc[2][0]);
        acc[2][1] = fmaf(a.z, b.y, acc[2][1]);
        acc[2][2] = fmaf(a.z, b.z, acc[2][2]);
        acc[2][3] = fmaf(a.z, b.w, acc[2][3]);
        acc[3][0] = fmaf(a.w, b.x, acc[3][0]);
        acc[3][1] = fmaf(a.w, b.y, acc[3][1]);
        acc[3][2] = fmaf(a.w, b.z, acc[3][2]);
        acc[3][3] = fmaf(a.w, b.w, acc[3][3]);
    }

    // combine k-splits into materialized logits (fire-and-forget REDG)
    float* dst = g_logits + (r0 + ty * 4) * BB + (c0 + tx * 4);
#pragma unroll
    for (int i = 0; i < 4; i++)
#pragma unroll
        for (int j = 0; j < 4; j++)
            atomicAdd(dst + i * BB + j, acc[i][j]);

    // ---- arrival: last 32 blocks do the LSE (all 256 blocks co-resident) --
    __shared__ unsigned int arrival;
    __syncthreads();                     // all this block's atomics issued
    if (tid == 0) {
        __threadfence();
        arrival = atomicAdd(&g_cnt, 1u);
    }
    __syncthreads();
    const unsigned int a_idx = arrival;

    if (a_idx >= 224u) {
        // spin until every block's combine is visible
        if (tid == 0) {
            while (*(volatile unsigned int*)&g_cnt < 256u) __nanosleep(40);
        }
        __syncthreads();
        __threadfence();

        // 8 warps, one row each: rows (a_idx-224)*8 .. +7
        const int lane = tid & 31;
        const int warp = tid >> 5;
        const int row  = (int)(a_idx - 224u) * 8 + warp;

        const float4* rp = reinterpret_cast<const float4*>(g_logits + row * BB);
        const float4 v0 = rp[lane * 2];
        const float4 v1 = rp[lane * 2 + 1];
        float e = __expf(v0.x) + __expf(v0.y) + __expf(v0.z) + __expf(v0.w)
                + __expf(v1.x) + __expf(v1.y) + __expf(v1.z) + __expf(v1.w);
#pragma unroll
        for (int o = 16; o; o >>= 1) e += __shfl_xor_sync(0xffffffffu, e, o);

        if (lane == 0) {
            const float dv = g_logits[row * BB + row];
            g_diag[row] = dv - logf(e);      // logp[row][row]
        }

        // ---- final mean by the last LSE slice ----
        __shared__ unsigned int arrival2;
        __syncthreads();
        if (tid == 0) {
            __threadfence();
            arrival2 = atomicAdd(&g_cnt2, 1u);
        }
        __syncthreads();

        if (arrival2 == 31u) {
            __threadfence();
            volatile float* vd = g_diag;
            float v = vd[tid];               // 256 threads == 256 rows
            __shared__ float red[8];
#pragma unroll
            for (int o = 16; o; o >>= 1) v += __shfl_xor_sync(0xffffffffu, v, o);
            if (lane == 0) red[warp] = v;
            __syncthreads();
            if (tid == 0) {
                float s = red[0];
#pragma unroll
                for (int i = 1; i < 8; i++) s += red[i];
                out[0] = -s * (1.0f / 256.0f);
            }
        }
    }
}

extern "C" void kernel_launch(void* const* d_in, const int* in_sizes, int n_in,
                              void* d_out, int out_size) {
    const float* face = (const float*)d_in[0];  // (256, 32, 512)
    const float* ner  = (const float*)d_in[1];  // (256, 32, 512)
    float* out = (float*)d_out;

    reduce_spans<<<2 * BB, 512>>>(face, ner);
    gemm_lse<<<256, 256>>>(out);
}

// round 12
// speedup vs baseline: 1.1364x; 1.1364x over previous
#include <cuda_runtime.h>
#include <math.h>

#define BB 256   // batch
#define NS 32    // spans
#define DD 512   // feature dim

#define KT 32    // k-chunk per gemm block (16 k-splits)

// Scratch (allocation-free rule: __device__ globals)
__device__ float g_A[BB * DD];        // ner span-sums [b][d] row-major, pre-scaled 1/1024
__device__ float g_F[BB * DD];        // face span-sums [c][d] row-major
__device__ float g_logits[BB * BB];   // materialized logits (atomic k-split combine)
__device__ float g_diag[BB];          // logp[b][b]
__device__ unsigned int g_cnt;        // lse arrival counter

// ---------------------------------------------------------------------------
// Kernel 1: span reductions. 512 blocks x 512 threads, one row per block.
// Thread = (t4 = tid&127 -> float4 of d, grp = tid>>7 -> 8 spans).
// The 8 span loads are EXPLICIT distinct registers with a pairwise tree sum
// so ptxas front-batches all 8 LDG.128 (MLP 8/thread); R8/R10's fused
// load-add chain had MLP~1 and left DRAM at 40%.
// Outputs row-major coalesced float4. Also zeroes g_logits / g_cnt.
// ---------------------------------------------------------------------------
__global__ void __launch_bounds__(512) reduce_spans(
        const float* __restrict__ face, const float* __restrict__ ner) {
    const int blk = blockIdx.x;
    const int tid = threadIdx.x;
    const int t4  = tid & 127;     // float4 index within row (128 * 4 = 512 d)
    const int grp = tid >> 7;      // span group 0..3 (8 spans each)

    // zero logits: 128 blocks x 512 threads = 65536 floats
    if (blk < 128) g_logits[blk * 512 + tid] = 0.f;
    if (blk == 128 && tid == 0) g_cnt = 0u;

    const bool is_ner = (blk < BB);
    const int row = is_ner ? blk : blk - BB;
    const float4* src = reinterpret_cast<const float4*>(
        (is_ner ? ner : face) + (size_t)row * NS * DD) + grp * 8 * (DD / 4) + t4;

    // 8 independent loads (distinct regs), then tree sum
    const float4 v0 = src[0 * (DD / 4)];
    const float4 v1 = src[1 * (DD / 4)];
    const float4 v2 = src[2 * (DD / 4)];
    const float4 v3 = src[3 * (DD / 4)];
    const float4 v4 = src[4 * (DD / 4)];
    const float4 v5 = src[5 * (DD / 4)];
    const float4 v6 = src[6 * (DD / 4)];
    const float4 v7 = src[7 * (DD / 4)];

    float4 s;
    {
        const float4 a01 = make_float4(v0.x + v1.x, v0.y + v1.y, v0.z + v1.z, v0.w + v1.w);
        const float4 a23 = make_float4(v2.x + v3.x, v2.y + v3.y, v2.z + v3.z, v2.w + v3.w);
        const float4 a45 = make_float4(v4.x + v5.x, v4.y + v5.y, v4.z + v5.z, v4.w + v5.w);
        const float4 a67 = make_float4(v6.x + v7.x, v6.y + v7.y, v6.z + v7.z, v6.w + v7.w);
        const float4 b0  = make_float4(a01.x + a23.x, a01.y + a23.y, a01.z + a23.z, a01.w + a23.w);
        const float4 b1  = make_float4(a45.x + a67.x, a45.y + a67.y, a45.z + a67.z, a45.w + a67.w);
        s = make_float4(b0.x + b1.x, b0.y + b1.y, b0.z + b1.z, b0.w + b1.w);
    }

    __shared__ float4 sp[3][128];
    if (grp > 0) sp[grp - 1][t4] = s;
    __syncthreads();

    if (grp == 0) {
#pragma unroll
        for (int i = 0; i < 3; i++) {
            float4 v = sp[i][t4];
            s.x += v.x; s.y += v.y; s.z += v.z; s.w += v.w;
        }
        if (is_ner) {
            const float inv = 1.0f / 1024.0f;   // fold the 1/(N1*N2) mean
            s.x *= inv; s.y *= inv; s.z *= inv; s.w *= inv;
            reinterpret_cast<float4*>(g_A + row * DD)[t4] = s;
        } else {
            reinterpret_cast<float4*>(g_F + row * DD)[t4] = s;
        }
    }
}

// ---------------------------------------------------------------------------
// Kernel 2: smem-staged register-blocked SGEMM partial (no fused LSE — the
// R10 spin-fusion regressed it 5 -> 14 us).
// Block = 64x64 C-tile, k-chunk of 32. Grid = 16 tiles x 16 k-splits = 256
// blocks x 256 threads. Staging: coalesced float4 reads of row-major tiles,
// transposed STS. Mainloop per k: 2 x LDS.128 + 16 FMA (4x4 reg tile).
// Combine via atomicAdd (REDG, fire-and-forget).
// ---------------------------------------------------------------------------
__global__ void gemm_part() {
    const int bx = blockIdx.x;
    const int kq = bx >> 4;              // k-split 0..15
    const int rt = (bx >> 2) & 3;        // row tile 0..3
    const int ct = bx & 3;               // col tile 0..3
    const int kb = kq * KT;
    const int r0 = rt * 64;
    const int c0 = ct * 64;
    const int tid = threadIdx.x;

    __shared__ float sA[KT][64];         // sA[k][row]  8 KB
    __shared__ float sB[KT][64];         // sB[k][col]  8 KB

#pragma unroll
    for (int j = 0; j < 2; j++) {
        const int idx = j * 256 + tid;   // 0..511
        const int row = idx >> 3;        // 0..63
        const int k4  = idx & 7;         // float4 along k-chunk
        const float4 va = *reinterpret_cast<const float4*>(
            g_A + (r0 + row) * DD + kb + k4 * 4);
        sA[k4 * 4 + 0][row] = va.x;
        sA[k4 * 4 + 1][row] = va.y;
        sA[k4 * 4 + 2][row] = va.z;
        sA[k4 * 4 + 3][row] = va.w;
        const float4 vb = *reinterpret_cast<const float4*>(
            g_F + (c0 + row) * DD + kb + k4 * 4);
        sB[k4 * 4 + 0][row] = vb.x;
        sB[k4 * 4 + 1][row] = vb.y;
        sB[k4 * 4 + 2][row] = vb.z;
        sB[k4 * 4 + 3][row] = vb.w;
    }
    __syncthreads();

    const int ty = tid >> 4;             // 0..15 -> rows r0 + ty*4 ..
    const int tx = tid & 15;             // 0..15 -> cols c0 + tx*4 ..

    float acc[4][4];
#pragma unroll
    for (int i = 0; i < 4; i++)
#pragma unroll
        for (int j = 0; j < 4; j++) acc[i][j] = 0.f;

#pragma unroll
    for (int k = 0; k < KT; k++) {
        const float4 a = *reinterpret_cast<const float4*>(&sA[k][ty * 4]);
        const float4 b = *reinterpret_cast<const float4*>(&sB[k][tx * 4]);
        acc[0][0] = fmaf(a.x, b.x, acc[0][0]);
        acc[0][1] = fmaf(a.x, b.y, acc[0][1]);
        acc[0][2] = fmaf(a.x, b.z, acc[0][2]);
        acc[0][3] = fmaf(a.x, b.w, acc[0][3]);
        acc[1][0] = fmaf(a.y, b.x, acc[1][0]);
        acc[1][1] = fmaf(a.y, b.y, acc[1][1]);
        acc[1][2] = fmaf(a.y, b.z, acc[1][2]);
        acc[1][3] = fmaf(a.y, b.w, acc[1][3]);
        acc[2][0] = fmaf(a.z, b.x, acc[2][0]);
        acc[2][1] = fmaf(a.z, b.y, acc[2][1]);
        acc[2][2] = fmaf(a.z, b.z, acc[2][2]);
        acc[2][3] = fmaf(a.z, b.w, acc[2][3]);
        acc[3][0] = fmaf(a.w, b.x, acc[3][0]);
        acc[3][1] = fmaf(a.w, b.y, acc[3][1]);
        acc[3][2] = fmaf(a.w, b.z, acc[3][2]);
        acc[3][3] = fmaf(a.w, b.w, acc[3][3]);
    }

    float* dst = g_logits + (r0 + ty * 4) * BB + (c0 + tx * 4);
#pragma unroll
    for (int i = 0; i < 4; i++)
#pragma unroll
        for (int j = 0; j < 4; j++)
            atomicAdd(dst + i * BB + j, acc[i][j]);
}

// ---------------------------------------------------------------------------
// Kernel 3: per-row LSE (no-max; logits are O(1), exp safe in fp32)
// + diagonal logp + last-block final mean.
// 32 blocks x 256 threads; one warp per row (8 rows/block).
// ---------------------------------------------------------------------------
__global__ void lse_final(float* __restrict__ out) {
    const int tid  = threadIdx.x;
    const int lane = tid & 31;
    const int warp = tid >> 5;
    const int row  = blockIdx.x * 8 + warp;

    const float4* rp = reinterpret_cast<const float4*>(g_logits + row * BB);
    const float4 v0 = rp[lane * 2];
    const float4 v1 = rp[lane * 2 + 1];
    float e = __expf(v0.x) + __expf(v0.y) + __expf(v0.z) + __expf(v0.w)
            + __expf(v1.x) + __expf(v1.y) + __expf(v1.z) + __expf(v1.w);
#pragma unroll
    for (int o = 16; o; o >>= 1) e += __shfl_xor_sync(0xffffffffu, e, o);

    if (lane == 0) {
        const float dv = g_logits[row * BB + row];
        g_diag[row] = dv - logf(e);      // logp[row][row]
    }

    // ---- last-arriving block computes the final mean ----
    __shared__ unsigned int arrival;
    __syncthreads();
    if (tid == 0) {
        __threadfence();
        arrival = atomicAdd(&g_cnt, 1u);
    }
    __syncthreads();

    if (arrival == 31u) {
        __threadfence();
        volatile float* vd = g_diag;
        float v = vd[tid];               // 256 threads == 256 rows
        __shared__ float red[8];
#pragma unroll
        for (int o = 16; o; o >>= 1) v += __shfl_xor_sync(0xffffffffu, v, o);
        if (lane == 0) red[warp] = v;
        __syncthreads();
        if (tid == 0) {
            float s = red[0];
#pragma unroll
            for (int i = 1; i < 8; i++) s += red[i];
            out[0] = -s * (1.0f / 256.0f);
        }
    }
}

extern "C" void kernel_launch(void* const* d_in, const int* in_sizes, int n_in,
                              void* d_out, int out_size) {
    const float* face = (const float*)d_in[0];  // (256, 32, 512)
    const float* ner  = (const float*)d_in[1];  // (256, 32, 512)
    float* out = (float*)d_out;

    reduce_spans<<<2 * BB, 512>>>(face, ner);
    gemm_part<<<256, 256>>>();
    lse_final<<<32, 256>>>(out);
}